// round 12
// baseline (speedup 1.0000x reference)
#include <cuda_runtime.h>
#include <cuda_bf16.h>
#include <math.h>
#include <stdint.h>

#define NTOK 2048   // B*N
#define DMODEL 1024
#define NSEQ 1024
#define NB 2
#define NH 16
#define HD 64
#define K3 (3 * DMODEL)   // extended split-precision K

// Output layout (float32, concatenated in reference return order)
#define OFF_FIN 0
#define OFF_FWD 2097152
#define OFF_BWD 2099200
#define OFF_STR 2101248

// scratch (device globals — no runtime allocation allowed)
__device__ float g_HF[NTOK * DMODEL];                      // head_features fp32
__device__ float g_partial[4][NB][DMODEL];                 // column-sum partials
// split-precision bf16 operands, extended-K layout (rows of length 3*DMODEL)
__device__ alignas(16) __nv_bfloat16 g_hS[NTOK * K3];      // h:  [hi | lo | hi]
__device__ alignas(16) __nv_bfloat16 g_WvS[DMODEL * K3];   // Wv: [hi | hi | lo]
__device__ alignas(16) __nv_bfloat16 g_WoS[DMODEL * K3];   // Wo: [hi | hi | lo]
__device__ alignas(16) __nv_bfloat16 g_multiS[NTOK * K3];  // multi: [hi | lo | hi]

// ---------------------------------------------------------------------------
// fp32 -> split bf16: one float4 at linear index i of `in` (row length 1024)
// ---------------------------------------------------------------------------
__device__ __forceinline__ void split_one(const float* __restrict__ in,
                                          __nv_bfloat16* __restrict__ out,
                                          int i, int o_lo, int o_hi2)
{
    int row = i >> 10;
    int k = i & 1023;
    float4 v = *(const float4*)(in + i);

    __nv_bfloat16 h0 = __float2bfloat16_rn(v.x);
    __nv_bfloat16 h1 = __float2bfloat16_rn(v.y);
    __nv_bfloat16 h2 = __float2bfloat16_rn(v.z);
    __nv_bfloat16 h3 = __float2bfloat16_rn(v.w);
    __nv_bfloat16 l0 = __float2bfloat16_rn(v.x - __bfloat162float(h0));
    __nv_bfloat16 l1 = __float2bfloat16_rn(v.y - __bfloat162float(h1));
    __nv_bfloat16 l2 = __float2bfloat16_rn(v.z - __bfloat162float(h2));
    __nv_bfloat16 l3 = __float2bfloat16_rn(v.w - __bfloat162float(h3));

    size_t base = (size_t)row * K3 + k;
    __nv_bfloat162 hA = {h0, h1}, hB = {h2, h3};
    __nv_bfloat162 lA = {l0, l1}, lB = {l2, l3};
    *(__nv_bfloat162*)(out + base)              = hA;
    *(__nv_bfloat162*)(out + base + 2)          = hB;
    *(__nv_bfloat162*)(out + base + o_hi2)      = hA;
    *(__nv_bfloat162*)(out + base + o_hi2 + 2)  = hB;
    *(__nv_bfloat162*)(out + base + o_lo)       = lA;
    *(__nv_bfloat162*)(out + base + o_lo + 2)   = lB;
}

// all three converts in one launch: h (512K float4s), Wv (256K), Wo (256K)
__global__ void split_all(const float* __restrict__ h,
                          const float* __restrict__ Wv,
                          const float* __restrict__ Wo,
                          __nv_bfloat16* __restrict__ phS,
                          __nv_bfloat16* __restrict__ pWvS,
                          __nv_bfloat16* __restrict__ pWoS)
{
    int id = blockIdx.x * blockDim.x + threadIdx.x;
    if (id < 524288) {
        split_one(h, phS, id * 4, DMODEL, 2 * DMODEL);              // A-layout
    } else if (id < 786432) {
        split_one(Wv, pWvS, (id - 524288) * 4, 2 * DMODEL, DMODEL); // B-layout
    } else if (id < 1048576) {
        split_one(Wo, pWoS, (id - 786432) * 4, 2 * DMODEL, DMODEL); // B-layout
    }
}

// ---------------------------------------------------------------------------
// bf16 mma.sync NT GEMM (R8 config): C[m][n] = sum_k A[m][k]*W[n][k].
// CTA 128x64, 4 warps (2x2), warp tile 64x32. GBK=64, 3-stage cp.async ring,
// ONE __syncthreads per chunk, register double-buffered ldmatrix fragments.
// XOR-swizzled 128B smem rows. grid 256 CTAs -> ~2 CTAs/SM.
// ---------------------------------------------------------------------------
#define TILE_M 128
#define TILE_N 64
#define GBK 64
#define NCH (K3 / GBK)                 // 48
#define NSTG 3
#define AREG_B (TILE_M * 128)          // 16384 bytes (A region, 128B rows)
#define BREG_B (TILE_N * 128)          //  8192 bytes (B region)
#define STG_BYTES (AREG_B + BREG_B)    // 24576
#define GEMM_SMEM (NSTG * STG_BYTES)   // 73728

__device__ __forceinline__ void cp16(uint32_t s, const void* g) {
    asm volatile("cp.async.cg.shared.global [%0], [%1], 16;\n" :: "r"(s), "l"(g));
}

__global__ __launch_bounds__(128) void gemm_bf16_nt(
    const __nv_bfloat16* __restrict__ A, const __nv_bfloat16* __restrict__ W,
    float* __restrict__ C, int Nn)
{
    extern __shared__ char dsm[];
    const int tid = threadIdx.x;
    const int lane = tid & 31;
    const int w = tid >> 5;
    const int m0 = blockIdx.y * TILE_M;
    const int n0 = blockIdx.x * TILE_N;
    const int wm = (w >> 1) * 64;   // 2 warp rows
    const int wn = (w & 1) * 32;    // 2 warp cols

    const uint32_t sBase = (uint32_t)__cvta_generic_to_shared(dsm);

    // fragment addressing (per-thread invariants)
    const int a_row = wm + (lane & 15);
    const int a_ch = (lane >> 4);          // 16B chunk offset within k-step
    const int b_row = wn + ((lane >> 4) & 1) * 8 + (lane & 7);
    const int b_ch = ((lane >> 3) & 1);

    float acc[4][4][4];
#pragma unroll
    for (int i = 0; i < 4; ++i)
#pragma unroll
        for (int j = 0; j < 4; ++j)
#pragma unroll
            for (int r = 0; r < 4; ++r) acc[i][j][r] = 0.0f;

    auto load_chunk = [&](int ck) {
        int stg = ck % NSTG;
        uint32_t sa = sBase + stg * STG_BYTES;
        uint32_t sb = sa + AREG_B;
        int k0 = ck * GBK;
#pragma unroll
        for (int j = 0; j < 8; ++j) {       // A: 1024 16B-chunks
            int c = tid + j * 128;
            int r = c >> 3;
            int ci = c & 7;
            cp16(sa + r * 128 + ((ci ^ (r & 7)) << 4),
                 A + (size_t)(m0 + r) * K3 + k0 + ci * 8);
        }
#pragma unroll
        for (int j = 0; j < 4; ++j) {       // B: 512 16B-chunks
            int c = tid + j * 128;
            int r = c >> 3;
            int ci = c & 7;
            cp16(sb + r * 128 + ((ci ^ (r & 7)) << 4),
                 W + (size_t)(n0 + r) * K3 + k0 + ci * 8);
        }
        asm volatile("cp.async.commit_group;\n");
    };

    load_chunk(0);
    load_chunk(1);

    for (int it = 0; it < NCH; ++it) {
        if (it < NCH - 1) asm volatile("cp.async.wait_group 1;\n");
        else              asm volatile("cp.async.wait_group 0;\n");
        __syncthreads();
        if (it + 2 < NCH) load_chunk(it + 2);  // overwrites buf consumed at it-1

        const uint32_t sa = sBase + (it % NSTG) * STG_BYTES;
        const uint32_t sb = sa + AREG_B;

        uint32_t af[2][4][4];
        uint32_t bf[2][4][2];

        auto ldfrag = [&](int buf, int ks) {
#pragma unroll
            for (int mi = 0; mi < 4; ++mi) {
                int r = a_row + mi * 16;
                int ci = ks * 2 + a_ch;
                uint32_t addr = sa + r * 128 + ((ci ^ (r & 7)) << 4);
                asm volatile(
                    "ldmatrix.sync.aligned.m8n8.x4.shared.b16 {%0,%1,%2,%3},[%4];\n"
                    : "=r"(af[buf][mi][0]), "=r"(af[buf][mi][1]),
                      "=r"(af[buf][mi][2]), "=r"(af[buf][mi][3])
                    : "r"(addr));
            }
#pragma unroll
            for (int np = 0; np < 2; ++np) {
                int r = b_row + np * 16;
                int ci = ks * 2 + b_ch;
                uint32_t addr = sb + r * 128 + ((ci ^ (r & 7)) << 4);
                uint32_t r0, r1, r2, r3;
                asm volatile(
                    "ldmatrix.sync.aligned.m8n8.x4.shared.b16 {%0,%1,%2,%3},[%4];\n"
                    : "=r"(r0), "=r"(r1), "=r"(r2), "=r"(r3) : "r"(addr));
                bf[buf][np * 2][0] = r0;     bf[buf][np * 2][1] = r1;
                bf[buf][np * 2 + 1][0] = r2; bf[buf][np * 2 + 1][1] = r3;
            }
        };

        ldfrag(0, 0);
#pragma unroll
        for (int ks = 0; ks < 4; ++ks) {
            if (ks < 3) ldfrag((ks + 1) & 1, ks + 1);  // prefetch next k-step
            const int cur = ks & 1;
#pragma unroll
            for (int mi = 0; mi < 4; ++mi)
#pragma unroll
                for (int ni = 0; ni < 4; ++ni) {
                    asm volatile(
                        "mma.sync.aligned.m16n8k16.row.col.f32.bf16.bf16.f32 "
                        "{%0,%1,%2,%3},{%4,%5,%6,%7},{%8,%9},{%0,%1,%2,%3};\n"
                        : "+f"(acc[mi][ni][0]), "+f"(acc[mi][ni][1]),
                          "+f"(acc[mi][ni][2]), "+f"(acc[mi][ni][3])
                        : "r"(af[cur][mi][0]), "r"(af[cur][mi][1]),
                          "r"(af[cur][mi][2]), "r"(af[cur][mi][3]),
                          "r"(bf[cur][ni][0]), "r"(bf[cur][ni][1]));
                }
        }
    }

    // epilogue: c-frag rows g / g+8, cols 2*(lane&3), 2*(lane&3)+1
    const int g = lane >> 2;
    const int cc = (lane & 3) * 2;
#pragma unroll
    for (int mi = 0; mi < 4; ++mi) {
#pragma unroll
        for (int ni = 0; ni < 4; ++ni) {
            int row = m0 + wm + mi * 16 + g;
            int col = n0 + wn + ni * 8 + cc;
            *(float2*)(C + (size_t)row * Nn + col) =
                make_float2(acc[mi][ni][0], acc[mi][ni][1]);
            *(float2*)(C + (size_t)(row + 8) * Nn + col) =
                make_float2(acc[mi][ni][2], acc[mi][ni][3]);
        }
    }
}

// ---------------------------------------------------------------------------
// Column partial sums of g_HF per batch (for the sequence mean)
// ---------------------------------------------------------------------------
__global__ void colmean_kernel()
{
    int c = blockIdx.x * 128 + threadIdx.x;
    int b = blockIdx.y;
    int r = blockIdx.z;
    const float* base = g_HF + (size_t)(b * NSEQ + r * 256) * DMODEL + c;
    float s = 0.0f;
#pragma unroll 4
    for (int row = 0; row < 256; ++row)
        s += base[(size_t)row * DMODEL];
    g_partial[r][b][c] = s;
}

// ---------------------------------------------------------------------------
// Fusion MLP with INLINE cvec, packed f32x2 FMAs.
// Per (64-token tile, head) block: two 64x64x64 GEMMs with exact GELU.
// B operands stored duplicated ({b,b} u64) in two smem arrays (<=2-way cfl).
// Writes multi directly in split-precision extended-K layout.
// ---------------------------------------------------------------------------
#define FUS_AT_OFF 0                      // float aT[64][68]   (17408 B)
#define FUS_BA_OFF 17408                  // u64 bA[64][36]     (18432 B)
#define FUS_BB_OFF 35840                  // u64 bB[64][36]     (18432 B)
#define FUS_MN_OFF 54272                  // float mnS[64]
#define FUS_CV_OFF 54528                  // float cvS[64]
#define FUS_SMEM   54784

#define FMA2(acc, a, b) \
    asm("fma.rn.f32x2 %0, %1, %2, %0;" : "+l"(acc) : "l"(a), "l"(b))
#define UNPK2(lo, hi, v) \
    asm("mov.b64 {%0,%1}, %2;" : "=f"(lo), "=f"(hi) : "l"(v))

__device__ __forceinline__ float gelu_exact(float x) {
    return 0.5f * x * (1.0f + erff(x * 0.70710678118654752f));
}

__global__ __launch_bounds__(256) void fusion_kernel(
    const float* __restrict__ fuW1, const float* __restrict__ fub1,
    const float* __restrict__ fuW2, const float* __restrict__ fub2)
{
    extern __shared__ char fsm[];
    float* aT = (float*)(fsm + FUS_AT_OFF);                         // [64][68]
    unsigned long long* bA = (unsigned long long*)(fsm + FUS_BA_OFF); // [64][36]
    unsigned long long* bB = (unsigned long long*)(fsm + FUS_BB_OFF); // [64][36]
    float* mnS = (float*)(fsm + FUS_MN_OFF);
    float* cvS = (float*)(fsm + FUS_CV_OFF);

    const int tid = threadIdx.x;
    const int m0 = blockIdx.x * 64;
    const int h = blockIdx.y;
    const int b = m0 >> 10;
    const int tr = tid >> 4;   // 0..15 -> tokens 4tr..4tr+3
    const int tc = tid & 15;   // 0..15 -> cols 4tc..4tc+3

    // sequence mean for this (b, h) slice
    if (tid < HD) {
        int c = h * HD + tid;
        mnS[tid] = (g_partial[0][b][c] + g_partial[1][b][c] +
                    g_partial[2][b][c] + g_partial[3][b][c]) * (1.0f / 1024.0f);
    }

    // hf tile transposed: aT[e][t]
    for (int idx = tid; idx < 64 * 64; idx += 256) {
        int t = idx >> 6, e = idx & 63;
        aT[e * 68 + t] = g_HF[(size_t)(m0 + t) * DMODEL + h * HD + e];
    }
    // W1a duplicated: col j, row e -> (j&2 ? bB : bA)[e][(j>>2)*2 + (j&1)]
    for (int idx = tid; idx < 64 * 64; idx += 256) {
        int j = idx >> 6, e = idx & 63;
        unsigned int bits =
            __float_as_uint(fuW1[(size_t)(h * HD + j) * (3 * HD) + e]);
        unsigned long long dup = ((unsigned long long)bits << 32) | bits;
        ((j & 2) ? bB : bA)[e * 36 + (j >> 2) * 2 + (j & 1)] = dup;
    }
    __syncthreads();

    // inline cvec: 4 threads per j-row, each covers 16 e's (float4 reads)
    {
        const int j = tid >> 2;          // 0..63
        const int t = tid & 3;           // 0..3
        const float* wrow = fuW1 + (size_t)(h * HD + j) * (3 * HD);
        float cacc = 0.0f;
#pragma unroll
        for (int q = 0; q < 4; ++q) {
            int e = t * 16 + q * 4;
            float4 wa = *(const float4*)(wrow + 64 + e);
            float4 wb = *(const float4*)(wrow + 128 + e);
            cacc = fmaf(wa.x + wb.x, mnS[e + 0], cacc);
            cacc = fmaf(wa.y + wb.y, mnS[e + 1], cacc);
            cacc = fmaf(wa.z + wb.z, mnS[e + 2], cacc);
            cacc = fmaf(wa.w + wb.w, mnS[e + 3], cacc);
        }
        cacc += __shfl_down_sync(0xffffffffu, cacc, 1, 4);
        cacc += __shfl_down_sync(0xffffffffu, cacc, 2, 4);
        if (t == 0) cvS[j] = cacc + fub1[h * HD + j];
    }

    // stage 1: packed f32x2 accumulation
    unsigned long long acc01[4], acc23[4];
#pragma unroll
    for (int j = 0; j < 4; ++j) { acc01[j] = 0ULL; acc23[j] = 0ULL; }

#pragma unroll
    for (int e = 0; e < HD; ++e) {
        ulonglong2 av = *(const ulonglong2*)&aT[e * 68 + tr * 4];
        ulonglong2 b01 = *(const ulonglong2*)&bA[e * 36 + tc * 2];
        ulonglong2 b23 = *(const ulonglong2*)&bB[e * 36 + tc * 2];
        FMA2(acc01[0], av.x, b01.x); FMA2(acc23[0], av.y, b01.x);
        FMA2(acc01[1], av.x, b01.y); FMA2(acc23[1], av.y, b01.y);
        FMA2(acc01[2], av.x, b23.x); FMA2(acc23[2], av.y, b23.x);
        FMA2(acc01[3], av.x, b23.y); FMA2(acc23[3], av.y, b23.y);
    }
    __syncthreads();   // aT/bA/bB reads done; cvS visible

    // gelu -> aT[j][t]
#pragma unroll
    for (int jj = 0; jj < 4; ++jj) {
        int j = tc * 4 + jj;
        float cv = cvS[j];
        float x0, x1, x2, x3;
        UNPK2(x0, x1, acc01[jj]);
        UNPK2(x2, x3, acc23[jj]);
        float4 gv;
        gv.x = gelu_exact(x0 + cv);
        gv.y = gelu_exact(x1 + cv);
        gv.z = gelu_exact(x2 + cv);
        gv.w = gelu_exact(x3 + cv);
        *(float4*)&aT[j * 68 + tr * 4] = gv;
    }
    // W2 duplicated: col f, row j
    for (int idx = tid; idx < 64 * 64; idx += 256) {
        int f = idx >> 6, j = idx & 63;
        unsigned int bits =
            __float_as_uint(fuW2[(size_t)(h * HD + f) * HD + j]);
        unsigned long long dup = ((unsigned long long)bits << 32) | bits;
        ((f & 2) ? bB : bA)[j * 36 + (f >> 2) * 2 + (f & 1)] = dup;
    }
    __syncthreads();

    // stage 2
#pragma unroll
    for (int j = 0; j < 4; ++j) { acc01[j] = 0ULL; acc23[j] = 0ULL; }

#pragma unroll
    for (int j = 0; j < HD; ++j) {
        ulonglong2 av = *(const ulonglong2*)&aT[j * 68 + tr * 4];
        ulonglong2 b01 = *(const ulonglong2*)&bA[j * 36 + tc * 2];
        ulonglong2 b23 = *(const ulonglong2*)&bB[j * 36 + tc * 2];
        FMA2(acc01[0], av.x, b01.x); FMA2(acc23[0], av.y, b01.x);
        FMA2(acc01[1], av.x, b01.y); FMA2(acc23[1], av.y, b01.y);
        FMA2(acc01[2], av.x, b23.x); FMA2(acc23[2], av.y, b23.x);
        FMA2(acc01[3], av.x, b23.y); FMA2(acc23[3], av.y, b23.y);
    }

    // unpack to xv[token][col]
    float xv[4][4];
#pragma unroll
    for (int jj = 0; jj < 4; ++jj) {
        UNPK2(xv[0][jj], xv[1][jj], acc01[jj]);
        UNPK2(xv[2][jj], xv[3][jj], acc23[jj]);
    }

    float bias[4];
#pragma unroll
    for (int jj = 0; jj < 4; ++jj) bias[jj] = fub2[h * HD + tc * 4 + jj];

#pragma unroll
    for (int i = 0; i < 4; ++i) {
        int t = tr * 4 + i;
        float x0 = xv[i][0] + bias[0];
        float x1 = xv[i][1] + bias[1];
        float x2 = xv[i][2] + bias[2];
        float x3 = xv[i][3] + bias[3];
        __nv_bfloat16 h0 = __float2bfloat16_rn(x0);
        __nv_bfloat16 h1 = __float2bfloat16_rn(x1);
        __nv_bfloat16 h2 = __float2bfloat16_rn(x2);
        __nv_bfloat16 h3 = __float2bfloat16_rn(x3);
        __nv_bfloat162 hA = {h0, h1}, hB = {h2, h3};
        __nv_bfloat162 lA = {__float2bfloat16_rn(x0 - __bfloat162float(h0)),
                             __float2bfloat16_rn(x1 - __bfloat162float(h1))};
        __nv_bfloat162 lB = {__float2bfloat16_rn(x2 - __bfloat162float(h2)),
                             __float2bfloat16_rn(x3 - __bfloat162float(h3))};
        size_t base = (size_t)(m0 + t) * K3 + h * HD + tc * 4;
        *(__nv_bfloat162*)&g_multiS[base]                  = hA;
        *(__nv_bfloat162*)&g_multiS[base + 2]              = hB;
        *(__nv_bfloat162*)&g_multiS[base + DMODEL]         = lA;
        *(__nv_bfloat162*)&g_multiS[base + DMODEL + 2]     = lB;
        *(__nv_bfloat162*)&g_multiS[base + 2 * DMODEL]     = hA;
        *(__nv_bfloat162*)&g_multiS[base + 2 * DMODEL + 2] = hB;
    }
}

// ---------------------------------------------------------------------------
// Trivial outputs: fwd/bwd targets + avg_strength (analytic constants)
// ---------------------------------------------------------------------------
__global__ void extras_kernel(const int* __restrict__ prev,
                              const float* __restrict__ cr,
                              float* __restrict__ out)
{
    int idx = blockIdx.x * blockDim.x + threadIdx.x;
    if (idx >= NTOK) return;
    int n = idx & (NSEQ - 1);

    float thr = floorf((float)NSEQ / (1.0f + expf(-cr[0])));
    float fwd = 511.0f;
    if ((float)n >= thr) {
        int p = prev[idx];
        p = p < 0 ? 0 : (p > NSEQ - 1 ? NSEQ - 1 : p);
        fwd = (float)p;
    }
    out[OFF_FWD + idx] = fwd;
    out[OFF_BWD + idx] = 511.0f;
    out[OFF_STR + idx] = 1.0f - logf(1.0f / (float)NSEQ + 1e-8f);
}

// ---------------------------------------------------------------------------
extern "C" void kernel_launch(void* const* d_in, const int* in_sizes, int n_in,
                              void* d_out, int out_size)
{
    const float* h    = (const float*)d_in[0];
    const int*   prev = (const int*)d_in[1];
    // d_in[2..9]: forward/backward encoder weights — provably dead code
    const float* Wv   = (const float*)d_in[10];
    const float* fuW1 = (const float*)d_in[11];
    const float* fub1 = (const float*)d_in[12];
    const float* fuW2 = (const float*)d_in[13];
    const float* fub2 = (const float*)d_in[14];
    const float* Wo   = (const float*)d_in[15];
    const float* cr   = (const float*)d_in[16];
    float* out = (float*)d_out;

    float *pHF = nullptr;
    __nv_bfloat16 *phS = nullptr, *pWvS = nullptr, *pWoS = nullptr, *pMS = nullptr;
    cudaGetSymbolAddress((void**)&pHF, g_HF);
    cudaGetSymbolAddress((void**)&phS, g_hS);
    cudaGetSymbolAddress((void**)&pWvS, g_WvS);
    cudaGetSymbolAddress((void**)&pWoS, g_WoS);
    cudaGetSymbolAddress((void**)&pMS, g_multiS);

    cudaFuncSetAttribute(gemm_bf16_nt,
                         cudaFuncAttributeMaxDynamicSharedMemorySize, GEMM_SMEM);
    cudaFuncSetAttribute(fusion_kernel,
                         cudaFuncAttributeMaxDynamicSharedMemorySize, FUS_SMEM);

    // 0) all split-precision converts in one launch
    split_all<<<4096, 256>>>(h, Wv, Wo, phS, pWvS, pWoS);

    dim3 g1(DMODEL / TILE_N, NTOK / TILE_M);   // (16, 16) = 256 CTAs

    // 1) head_features = h @ Wv^T  (split bf16: hi*hi + lo*hi + hi*lo)
    gemm_bf16_nt<<<g1, 128, GEMM_SMEM>>>(phS, pWvS, pHF, DMODEL);

    // 2) sequence-mean partials per batch
    colmean_kernel<<<dim3(DMODEL / 128, NB, 4), 128>>>();

    // 3) fusion MLP (inline cvec, f32x2) -> g_multiS (split layout)
    fusion_kernel<<<dim3(NTOK / 64, NH), 256, FUS_SMEM>>>(fuW1, fub1, fuW2, fub2);

    // 4) final_output = multi @ Wo^T
    gemm_bf16_nt<<<g1, 128, GEMM_SMEM>>>(pMS, pWoS, out, DMODEL);

    // 5) analytic outputs
    extras_kernel<<<(NTOK + 255) / 256, 256>>>(prev, cr, out);
}

// round 13
// speedup vs baseline: 1.2407x; 1.2407x over previous
#include <cuda_runtime.h>
#include <cuda_bf16.h>
#include <math.h>
#include <stdint.h>

#define NTOK 2048   // B*N
#define DMODEL 1024
#define NSEQ 1024
#define NB 2
#define NH 16
#define HD 64
#define K3 (3 * DMODEL)   // extended split-precision K

// Output layout (float32, concatenated in reference return order)
#define OFF_FIN 0
#define OFF_FWD 2097152
#define OFF_BWD 2099200
#define OFF_STR 2101248

// scratch (device globals — no runtime allocation allowed)
__device__ float g_HF[NTOK * DMODEL];                      // head_features fp32
__device__ float g_cp[32][DMODEL];                         // per (m-tile, warp-row) colsums
// split-precision bf16 operands, extended-K layout (rows of length 3*DMODEL)
__device__ alignas(16) __nv_bfloat16 g_hS[NTOK * K3];      // h:  [hi | lo | hi]
__device__ alignas(16) __nv_bfloat16 g_WvS[DMODEL * K3];   // Wv: [hi | hi | lo]
__device__ alignas(16) __nv_bfloat16 g_WoS[DMODEL * K3];   // Wo: [hi | hi | lo]
__device__ alignas(16) __nv_bfloat16 g_multiS[NTOK * K3];  // multi: [hi | lo | hi]

// ---------------------------------------------------------------------------
// fp32 -> split bf16: one float4 at linear index i of `in` (row length 1024)
// ---------------------------------------------------------------------------
__device__ __forceinline__ void split_one(const float* __restrict__ in,
                                          __nv_bfloat16* __restrict__ out,
                                          int i, int o_lo, int o_hi2)
{
    int row = i >> 10;
    int k = i & 1023;
    float4 v = *(const float4*)(in + i);

    __nv_bfloat16 h0 = __float2bfloat16_rn(v.x);
    __nv_bfloat16 h1 = __float2bfloat16_rn(v.y);
    __nv_bfloat16 h2 = __float2bfloat16_rn(v.z);
    __nv_bfloat16 h3 = __float2bfloat16_rn(v.w);
    __nv_bfloat16 l0 = __float2bfloat16_rn(v.x - __bfloat162float(h0));
    __nv_bfloat16 l1 = __float2bfloat16_rn(v.y - __bfloat162float(h1));
    __nv_bfloat16 l2 = __float2bfloat16_rn(v.z - __bfloat162float(h2));
    __nv_bfloat16 l3 = __float2bfloat16_rn(v.w - __bfloat162float(h3));

    size_t base = (size_t)row * K3 + k;
    __nv_bfloat162 hA = {h0, h1}, hB = {h2, h3};
    __nv_bfloat162 lA = {l0, l1}, lB = {l2, l3};
    *(__nv_bfloat162*)(out + base)              = hA;
    *(__nv_bfloat162*)(out + base + 2)          = hB;
    *(__nv_bfloat162*)(out + base + o_hi2)      = hA;
    *(__nv_bfloat162*)(out + base + o_hi2 + 2)  = hB;
    *(__nv_bfloat162*)(out + base + o_lo)       = lA;
    *(__nv_bfloat162*)(out + base + o_lo + 2)   = lB;
}

// all three converts in one launch: h (512K float4s), Wv (256K), Wo (256K)
__global__ void split_all(const float* __restrict__ h,
                          const float* __restrict__ Wv,
                          const float* __restrict__ Wo,
                          __nv_bfloat16* __restrict__ phS,
                          __nv_bfloat16* __restrict__ pWvS,
                          __nv_bfloat16* __restrict__ pWoS)
{
    int id = blockIdx.x * blockDim.x + threadIdx.x;
    if (id < 524288) {
        split_one(h, phS, id * 4, DMODEL, 2 * DMODEL);              // A-layout
    } else if (id < 786432) {
        split_one(Wv, pWvS, (id - 524288) * 4, 2 * DMODEL, DMODEL); // B-layout
    } else if (id < 1048576) {
        split_one(Wo, pWoS, (id - 786432) * 4, 2 * DMODEL, DMODEL); // B-layout
    }
}

// ---------------------------------------------------------------------------
// bf16 mma.sync NT GEMM (R8 config): C[m][n] = sum_k A[m][k]*W[n][k].
// CTA 128x64, 4 warps (2x2), warp tile 64x32. GBK=64, 3-stage cp.async ring,
// ONE __syncthreads per chunk, register double-buffered ldmatrix fragments.
// XOR-swizzled 128B smem rows. grid 256 CTAs -> ~2 CTAs/SM.
// do_colsum: also emit per-(CTA m-tile, warp-row) column sums to g_cp.
// ---------------------------------------------------------------------------
#define TILE_M 128
#define TILE_N 64
#define GBK 64
#define NCH (K3 / GBK)                 // 48
#define NSTG 3
#define AREG_B (TILE_M * 128)          // 16384 bytes (A region, 128B rows)
#define BREG_B (TILE_N * 128)          //  8192 bytes (B region)
#define STG_BYTES (AREG_B + BREG_B)    // 24576
#define GEMM_SMEM (NSTG * STG_BYTES)   // 73728

__device__ __forceinline__ void cp16(uint32_t s, const void* g) {
    asm volatile("cp.async.cg.shared.global [%0], [%1], 16;\n" :: "r"(s), "l"(g));
}

__global__ __launch_bounds__(128) void gemm_bf16_nt(
    const __nv_bfloat16* __restrict__ A, const __nv_bfloat16* __restrict__ W,
    float* __restrict__ C, int Nn, int do_colsum)
{
    extern __shared__ char dsm[];
    const int tid = threadIdx.x;
    const int lane = tid & 31;
    const int w = tid >> 5;
    const int m0 = blockIdx.y * TILE_M;
    const int n0 = blockIdx.x * TILE_N;
    const int wm = (w >> 1) * 64;   // 2 warp rows
    const int wn = (w & 1) * 32;    // 2 warp cols

    const uint32_t sBase = (uint32_t)__cvta_generic_to_shared(dsm);

    // fragment addressing (per-thread invariants)
    const int a_row = wm + (lane & 15);
    const int a_ch = (lane >> 4);          // 16B chunk offset within k-step
    const int b_row = wn + ((lane >> 4) & 1) * 8 + (lane & 7);
    const int b_ch = ((lane >> 3) & 1);

    float acc[4][4][4];
#pragma unroll
    for (int i = 0; i < 4; ++i)
#pragma unroll
        for (int j = 0; j < 4; ++j)
#pragma unroll
            for (int r = 0; r < 4; ++r) acc[i][j][r] = 0.0f;

    auto load_chunk = [&](int ck) {
        int stg = ck % NSTG;
        uint32_t sa = sBase + stg * STG_BYTES;
        uint32_t sb = sa + AREG_B;
        int k0 = ck * GBK;
#pragma unroll
        for (int j = 0; j < 8; ++j) {       // A: 1024 16B-chunks
            int c = tid + j * 128;
            int r = c >> 3;
            int ci = c & 7;
            cp16(sa + r * 128 + ((ci ^ (r & 7)) << 4),
                 A + (size_t)(m0 + r) * K3 + k0 + ci * 8);
        }
#pragma unroll
        for (int j = 0; j < 4; ++j) {       // B: 512 16B-chunks
            int c = tid + j * 128;
            int r = c >> 3;
            int ci = c & 7;
            cp16(sb + r * 128 + ((ci ^ (r & 7)) << 4),
                 W + (size_t)(n0 + r) * K3 + k0 + ci * 8);
        }
        asm volatile("cp.async.commit_group;\n");
    };

    load_chunk(0);
    load_chunk(1);

    for (int it = 0; it < NCH; ++it) {
        if (it < NCH - 1) asm volatile("cp.async.wait_group 1;\n");
        else              asm volatile("cp.async.wait_group 0;\n");
        __syncthreads();
        if (it + 2 < NCH) load_chunk(it + 2);  // overwrites buf consumed at it-1

        const uint32_t sa = sBase + (it % NSTG) * STG_BYTES;
        const uint32_t sb = sa + AREG_B;

        uint32_t af[2][4][4];
        uint32_t bf[2][4][2];

        auto ldfrag = [&](int buf, int ks) {
#pragma unroll
            for (int mi = 0; mi < 4; ++mi) {
                int r = a_row + mi * 16;
                int ci = ks * 2 + a_ch;
                uint32_t addr = sa + r * 128 + ((ci ^ (r & 7)) << 4);
                asm volatile(
                    "ldmatrix.sync.aligned.m8n8.x4.shared.b16 {%0,%1,%2,%3},[%4];\n"
                    : "=r"(af[buf][mi][0]), "=r"(af[buf][mi][1]),
                      "=r"(af[buf][mi][2]), "=r"(af[buf][mi][3])
                    : "r"(addr));
            }
#pragma unroll
            for (int np = 0; np < 2; ++np) {
                int r = b_row + np * 16;
                int ci = ks * 2 + b_ch;
                uint32_t addr = sb + r * 128 + ((ci ^ (r & 7)) << 4);
                uint32_t r0, r1, r2, r3;
                asm volatile(
                    "ldmatrix.sync.aligned.m8n8.x4.shared.b16 {%0,%1,%2,%3},[%4];\n"
                    : "=r"(r0), "=r"(r1), "=r"(r2), "=r"(r3) : "r"(addr));
                bf[buf][np * 2][0] = r0;     bf[buf][np * 2][1] = r1;
                bf[buf][np * 2 + 1][0] = r2; bf[buf][np * 2 + 1][1] = r3;
            }
        };

        ldfrag(0, 0);
#pragma unroll
        for (int ks = 0; ks < 4; ++ks) {
            if (ks < 3) ldfrag((ks + 1) & 1, ks + 1);  // prefetch next k-step
            const int cur = ks & 1;
#pragma unroll
            for (int mi = 0; mi < 4; ++mi)
#pragma unroll
                for (int ni = 0; ni < 4; ++ni) {
                    asm volatile(
                        "mma.sync.aligned.m16n8k16.row.col.f32.bf16.bf16.f32 "
                        "{%0,%1,%2,%3},{%4,%5,%6,%7},{%8,%9},{%0,%1,%2,%3};\n"
                        : "+f"(acc[mi][ni][0]), "+f"(acc[mi][ni][1]),
                          "+f"(acc[mi][ni][2]), "+f"(acc[mi][ni][3])
                        : "r"(af[cur][mi][0]), "r"(af[cur][mi][1]),
                          "r"(af[cur][mi][2]), "r"(af[cur][mi][3]),
                          "r"(bf[cur][ni][0]), "r"(bf[cur][ni][1]));
                }
        }
    }

    // epilogue: c-frag rows g / g+8, cols 2*(lane&3), 2*(lane&3)+1
    const int g = lane >> 2;
    const int cc = (lane & 3) * 2;
#pragma unroll
    for (int mi = 0; mi < 4; ++mi) {
#pragma unroll
        for (int ni = 0; ni < 4; ++ni) {
            int row = m0 + wm + mi * 16 + g;
            int col = n0 + wn + ni * 8 + cc;
            *(float2*)(C + (size_t)row * Nn + col) =
                make_float2(acc[mi][ni][0], acc[mi][ni][1]);
            *(float2*)(C + (size_t)(row + 8) * Nn + col) =
                make_float2(acc[mi][ni][2], acc[mi][ni][3]);
        }
    }

    // fused column sums over this warp's 64 rows (deterministic, no atomics)
    if (do_colsum) {
        float cs[4][2];
#pragma unroll
        for (int ni = 0; ni < 4; ++ni) {
            float s0 = 0.0f, s1 = 0.0f;
#pragma unroll
            for (int mi = 0; mi < 4; ++mi) {
                s0 += acc[mi][ni][0] + acc[mi][ni][2];
                s1 += acc[mi][ni][1] + acc[mi][ni][3];
            }
            cs[ni][0] = s0;
            cs[ni][1] = s1;
        }
#pragma unroll
        for (int off = 4; off < 32; off <<= 1) {
#pragma unroll
            for (int ni = 0; ni < 4; ++ni) {
                cs[ni][0] += __shfl_xor_sync(0xffffffffu, cs[ni][0], off);
                cs[ni][1] += __shfl_xor_sync(0xffffffffu, cs[ni][1], off);
            }
        }
        if (lane < 4) {
            int slot = (m0 >> 7) * 2 + (wm >> 6);   // 0..31
#pragma unroll
            for (int ni = 0; ni < 4; ++ni) {
                g_cp[slot][n0 + wn + ni * 8 + lane * 2]     = cs[ni][0];
                g_cp[slot][n0 + wn + ni * 8 + lane * 2 + 1] = cs[ni][1];
            }
        }
    }
}

// ---------------------------------------------------------------------------
// Fusion MLP with INLINE cvec (R10 version; mean from g_cp partials).
// Per (64-token tile, head) block: two 64x64x64 GEMMs with exact GELU.
// Writes multi directly in split-precision extended-K layout.
// ---------------------------------------------------------------------------
__device__ __forceinline__ float gelu_exact(float x) {
    return 0.5f * x * (1.0f + erff(x * 0.70710678118654752f));
}

__global__ __launch_bounds__(256) void fusion_kernel(
    const float* __restrict__ fuW1, const float* __restrict__ fub1,
    const float* __restrict__ fuW2, const float* __restrict__ fub2)
{
    __shared__ float aT[HD][68];
    __shared__ float bT[HD][68];
    __shared__ float mnS[HD];
    __shared__ float cvS[HD];

    const int tid = threadIdx.x;
    const int m0 = blockIdx.x * 64;
    const int h = blockIdx.y;
    const int b = m0 >> 10;
    const int tr = tid >> 4;
    const int tc = tid & 15;

    // sequence mean for this (b, h) slice from the 16 GEMM-epilogue partials
    if (tid < HD) {
        int c = h * HD + tid;
        float s = 0.0f;
#pragma unroll
        for (int q = 0; q < 16; ++q)
            s += g_cp[b * 16 + q][c];
        mnS[tid] = s * (1.0f / 1024.0f);
    }

    for (int idx = tid; idx < 64 * 64; idx += 256) {
        int t = idx >> 6, e = idx & 63;
        aT[e][t] = g_HF[(size_t)(m0 + t) * DMODEL + h * HD + e];
    }
    for (int idx = tid; idx < 64 * 64; idx += 256) {
        int j = idx >> 6, e = idx & 63;
        bT[e][j] = fuW1[(size_t)(h * HD + j) * (3 * HD) + e];
    }
    __syncthreads();

    // inline cvec: 4 threads per j-row, each covers 16 e's (float4 reads)
    {
        const int j = tid >> 2;          // 0..63
        const int t = tid & 3;           // 0..3
        const float* wrow = fuW1 + (size_t)(h * HD + j) * (3 * HD);
        float cacc = 0.0f;
#pragma unroll
        for (int q = 0; q < 4; ++q) {
            int e = t * 16 + q * 4;
            float4 wa = *(const float4*)(wrow + 64 + e);
            float4 wb = *(const float4*)(wrow + 128 + e);
            cacc = fmaf(wa.x + wb.x, mnS[e + 0], cacc);
            cacc = fmaf(wa.y + wb.y, mnS[e + 1], cacc);
            cacc = fmaf(wa.z + wb.z, mnS[e + 2], cacc);
            cacc = fmaf(wa.w + wb.w, mnS[e + 3], cacc);
        }
        cacc += __shfl_down_sync(0xffffffffu, cacc, 1, 4);
        cacc += __shfl_down_sync(0xffffffffu, cacc, 2, 4);
        if (t == 0) cvS[j] = cacc + fub1[h * HD + j];
    }

    float acc[4][4];
#pragma unroll
    for (int i = 0; i < 4; ++i)
#pragma unroll
        for (int j = 0; j < 4; ++j) acc[i][j] = 0.0f;

#pragma unroll
    for (int e = 0; e < HD; ++e) {
        float4 a = *(const float4*)&aT[e][tr * 4];
        float4 bv = *(const float4*)&bT[e][tc * 4];
        float ra[4] = {a.x, a.y, a.z, a.w};
        float rb[4] = {bv.x, bv.y, bv.z, bv.w};
#pragma unroll
        for (int i = 0; i < 4; ++i)
#pragma unroll
            for (int j = 0; j < 4; ++j)
                acc[i][j] = fmaf(ra[i], rb[j], acc[i][j]);
    }
    __syncthreads();   // aT/bT reads done; cvS written (synced here)

#pragma unroll
    for (int jj = 0; jj < 4; ++jj) {
        int j = tc * 4 + jj;
        float cv = cvS[j];
        float4 gv;
        gv.x = gelu_exact(acc[0][jj] + cv);
        gv.y = gelu_exact(acc[1][jj] + cv);
        gv.z = gelu_exact(acc[2][jj] + cv);
        gv.w = gelu_exact(acc[3][jj] + cv);
        *(float4*)&aT[j][tr * 4] = gv;
    }
    for (int idx = tid; idx < 64 * 64; idx += 256) {
        int f = idx >> 6, j = idx & 63;
        bT[j][f] = fuW2[(size_t)(h * HD + f) * HD + j];
    }
    __syncthreads();

    float acc2[4][4];
#pragma unroll
    for (int i = 0; i < 4; ++i)
#pragma unroll
        for (int j = 0; j < 4; ++j) acc2[i][j] = 0.0f;

#pragma unroll
    for (int j = 0; j < HD; ++j) {
        float4 a = *(const float4*)&aT[j][tr * 4];
        float4 bv = *(const float4*)&bT[j][tc * 4];
        float ra[4] = {a.x, a.y, a.z, a.w};
        float rb[4] = {bv.x, bv.y, bv.z, bv.w};
#pragma unroll
        for (int i = 0; i < 4; ++i)
#pragma unroll
            for (int jj = 0; jj < 4; ++jj)
                acc2[i][jj] = fmaf(ra[i], rb[jj], acc2[i][jj]);
    }

    float bias[4];
#pragma unroll
    for (int jj = 0; jj < 4; ++jj) bias[jj] = fub2[h * HD + tc * 4 + jj];

#pragma unroll
    for (int i = 0; i < 4; ++i) {
        int t = tr * 4 + i;
        float x0 = acc2[i][0] + bias[0];
        float x1 = acc2[i][1] + bias[1];
        float x2 = acc2[i][2] + bias[2];
        float x3 = acc2[i][3] + bias[3];
        __nv_bfloat16 h0 = __float2bfloat16_rn(x0);
        __nv_bfloat16 h1 = __float2bfloat16_rn(x1);
        __nv_bfloat16 h2 = __float2bfloat16_rn(x2);
        __nv_bfloat16 h3 = __float2bfloat16_rn(x3);
        __nv_bfloat162 hA = {h0, h1}, hB = {h2, h3};
        __nv_bfloat162 lA = {__float2bfloat16_rn(x0 - __bfloat162float(h0)),
                             __float2bfloat16_rn(x1 - __bfloat162float(h1))};
        __nv_bfloat162 lB = {__float2bfloat16_rn(x2 - __bfloat162float(h2)),
                             __float2bfloat16_rn(x3 - __bfloat162float(h3))};
        size_t base = (size_t)(m0 + t) * K3 + h * HD + tc * 4;
        *(__nv_bfloat162*)&g_multiS[base]                  = hA;
        *(__nv_bfloat162*)&g_multiS[base + 2]              = hB;
        *(__nv_bfloat162*)&g_multiS[base + DMODEL]         = lA;
        *(__nv_bfloat162*)&g_multiS[base + DMODEL + 2]     = lB;
        *(__nv_bfloat162*)&g_multiS[base + 2 * DMODEL]     = hA;
        *(__nv_bfloat162*)&g_multiS[base + 2 * DMODEL + 2] = hB;
    }
}

// ---------------------------------------------------------------------------
// Trivial outputs: fwd/bwd targets + avg_strength (analytic constants)
// ---------------------------------------------------------------------------
__global__ void extras_kernel(const int* __restrict__ prev,
                              const float* __restrict__ cr,
                              float* __restrict__ out)
{
    int idx = blockIdx.x * blockDim.x + threadIdx.x;
    if (idx >= NTOK) return;
    int n = idx & (NSEQ - 1);

    float thr = floorf((float)NSEQ / (1.0f + expf(-cr[0])));
    float fwd = 511.0f;
    if ((float)n >= thr) {
        int p = prev[idx];
        p = p < 0 ? 0 : (p > NSEQ - 1 ? NSEQ - 1 : p);
        fwd = (float)p;
    }
    out[OFF_FWD + idx] = fwd;
    out[OFF_BWD + idx] = 511.0f;
    out[OFF_STR + idx] = 1.0f - logf(1.0f / (float)NSEQ + 1e-8f);
}

// ---------------------------------------------------------------------------
extern "C" void kernel_launch(void* const* d_in, const int* in_sizes, int n_in,
                              void* d_out, int out_size)
{
    const float* h    = (const float*)d_in[0];
    const int*   prev = (const int*)d_in[1];
    // d_in[2..9]: forward/backward encoder weights — provably dead code
    const float* Wv   = (const float*)d_in[10];
    const float* fuW1 = (const float*)d_in[11];
    const float* fub1 = (const float*)d_in[12];
    const float* fuW2 = (const float*)d_in[13];
    const float* fub2 = (const float*)d_in[14];
    const float* Wo   = (const float*)d_in[15];
    const float* cr   = (const float*)d_in[16];
    float* out = (float*)d_out;

    float *pHF = nullptr;
    __nv_bfloat16 *phS = nullptr, *pWvS = nullptr, *pWoS = nullptr, *pMS = nullptr;
    cudaGetSymbolAddress((void**)&pHF, g_HF);
    cudaGetSymbolAddress((void**)&phS, g_hS);
    cudaGetSymbolAddress((void**)&pWvS, g_WvS);
    cudaGetSymbolAddress((void**)&pWoS, g_WoS);
    cudaGetSymbolAddress((void**)&pMS, g_multiS);

    cudaFuncSetAttribute(gemm_bf16_nt,
                         cudaFuncAttributeMaxDynamicSharedMemorySize, GEMM_SMEM);

    // 0) all split-precision converts in one launch
    split_all<<<4096, 256>>>(h, Wv, Wo, phS, pWvS, pWoS);

    dim3 g1(DMODEL / TILE_N, NTOK / TILE_M);   // (16, 16) = 256 CTAs

    // 1) head_features = h @ Wv^T  (split bf16) + fused column sums
    gemm_bf16_nt<<<g1, 128, GEMM_SMEM>>>(phS, pWvS, pHF, DMODEL, 1);

    // 2) fusion MLP (inline cvec; mean from g_cp) -> g_multiS (split layout)
    fusion_kernel<<<dim3(NTOK / 64, NH), 256>>>(fuW1, fub1, fuW2, fub2);

    // 3) final_output = multi @ Wo^T
    gemm_bf16_nt<<<g1, 128, GEMM_SMEM>>>(pMS, pWoS, out, DMODEL, 0);

    // 4) analytic outputs
    extras_kernel<<<(NTOK + 255) / 256, 256>>>(prev, cr, out);
}

// round 14
// speedup vs baseline: 1.6243x; 1.3092x over previous
#include <cuda_runtime.h>
#include <cuda_bf16.h>
#include <math.h>
#include <stdint.h>

#define NTOK 2048   // B*N
#define DMODEL 1024
#define NSEQ 1024
#define NB 2
#define NH 16
#define HD 64

// Output layout (float32, concatenated in reference return order)
#define OFF_FIN 0
#define OFF_FWD 2097152
#define OFF_BWD 2099200
#define OFF_STR 2101248

// scratch (device globals — no runtime allocation allowed)
__device__ float g_HF[NTOK * DMODEL];                     // head_features fp32
__device__ float g_cp[32][DMODEL];                        // per (m-tile, warp-row) colsums
__device__ alignas(16) float g_hT[NTOK * DMODEL];         // h, tf32-rounded
__device__ alignas(16) float g_WvT[DMODEL * DMODEL];      // Wv, tf32-rounded
__device__ alignas(16) float g_WoT[DMODEL * DMODEL];      // Wo, tf32-rounded
__device__ alignas(16) float g_multiT[NTOK * DMODEL];     // multi, tf32-rounded

// ---------------------------------------------------------------------------
// fp32 -> tf32 (RN) converts, all three tensors in one launch
// ---------------------------------------------------------------------------
__device__ __forceinline__ float tf32r(float x) {
    uint32_t r;
    asm("cvt.rn.tf32.f32 %0, %1;" : "=r"(r) : "f"(x));
    return __uint_as_float(r);
}

__device__ __forceinline__ void cvt4(const float* __restrict__ in,
                                     float* __restrict__ out, int i) {
    float4 v = *(const float4*)(in + i);
    v.x = tf32r(v.x); v.y = tf32r(v.y); v.z = tf32r(v.z); v.w = tf32r(v.w);
    *(float4*)(out + i) = v;
}

__global__ void tf32_all(const float* __restrict__ h,
                         const float* __restrict__ Wv,
                         const float* __restrict__ Wo)
{
    int id = blockIdx.x * blockDim.x + threadIdx.x;
    if (id < 524288)        cvt4(h,  g_hT,  id * 4);
    else if (id < 786432)   cvt4(Wv, g_WvT, (id - 524288) * 4);
    else if (id < 1048576)  cvt4(Wo, g_WoT, (id - 786432) * 4);
}

// ---------------------------------------------------------------------------
// tf32 mma.sync NT GEMM: C[m][n] = sum_k A[m][k]*W[n][k], fp32 accum. K=1024.
// CTA 128x64, 4 warps (2x2), warp tile 64x32, mma m16n8k8.
// Chunks of 32 floats (128B rows), 3-stage cp.async ring, one sync/chunk.
// XOR-swizzled 16B chunks. ldmatrix.b16 delivers tf32 frags (8x4 tf32 tiles).
// do_colsum: fused per-(m-tile, warp-row) column sums into g_cp.
// ---------------------------------------------------------------------------
#define TILE_M 128
#define TILE_N 64
#define GBK 32                         // floats per chunk (128B rows)
#define NCH (DMODEL / GBK)             // 32
#define NSTG 3
#define AREG_B (TILE_M * 128)          // 16384 bytes
#define BREG_B (TILE_N * 128)          //  8192 bytes
#define STG_BYTES (AREG_B + BREG_B)    // 24576
#define GEMM_SMEM (NSTG * STG_BYTES)   // 73728

__device__ __forceinline__ void cp16(uint32_t s, const void* g) {
    asm volatile("cp.async.cg.shared.global [%0], [%1], 16;\n" :: "r"(s), "l"(g));
}

__global__ __launch_bounds__(128) void gemm_tf32_nt(
    const float* __restrict__ A, const float* __restrict__ W,
    float* __restrict__ C, int Nn, int do_colsum)
{
    extern __shared__ char dsm[];
    const int tid = threadIdx.x;
    const int lane = tid & 31;
    const int w = tid >> 5;
    const int m0 = blockIdx.y * TILE_M;
    const int n0 = blockIdx.x * TILE_N;
    const int wm = (w >> 1) * 64;   // 2 warp rows
    const int wn = (w & 1) * 32;    // 2 warp cols

    const uint32_t sBase = (uint32_t)__cvta_generic_to_shared(dsm);

    // ldmatrix per-lane addressing (tf32 via b16 tiles; 16B = 4 tf32)
    // A x4: tiles = quadrants (r0..7,k0..3),(r8..15,k0..3),(r0..7,k4..7),(r8..15,k4..7)
    const int a_row = wm + (lane & 7) + ((lane >> 3) & 1) * 8;  // + mi*16
    const int a_c4 = (lane >> 4) & 1;                            // k4 half
    // B x4: tiles = (n0..7,k0..3),(n0..7,k4..7),(n8..15,k0..3),(n8..15,k4..7)
    const int b_row = wn + (lane & 7) + ((lane >> 4) & 1) * 8;  // + np*16
    const int b_c4 = (lane >> 3) & 1;

    float acc[4][4][4];
#pragma unroll
    for (int i = 0; i < 4; ++i)
#pragma unroll
        for (int j = 0; j < 4; ++j)
#pragma unroll
            for (int r = 0; r < 4; ++r) acc[i][j][r] = 0.0f;

    auto load_chunk = [&](int ck) {
        int stg = ck % NSTG;
        uint32_t sa = sBase + stg * STG_BYTES;
        uint32_t sb = sa + AREG_B;
        int k0 = ck * GBK;
#pragma unroll
        for (int j = 0; j < 8; ++j) {       // A: 1024 16B-chunks
            int c = tid + j * 128;
            int r = c >> 3;
            int ci = c & 7;
            cp16(sa + r * 128 + ((ci ^ (r & 7)) << 4),
                 A + (size_t)(m0 + r) * DMODEL + k0 + ci * 4);
        }
#pragma unroll
        for (int j = 0; j < 4; ++j) {       // B: 512 16B-chunks
            int c = tid + j * 128;
            int r = c >> 3;
            int ci = c & 7;
            cp16(sb + r * 128 + ((ci ^ (r & 7)) << 4),
                 W + (size_t)(n0 + r) * DMODEL + k0 + ci * 4);
        }
        asm volatile("cp.async.commit_group;\n");
    };

    load_chunk(0);
    load_chunk(1);

    for (int it = 0; it < NCH; ++it) {
        if (it < NCH - 1) asm volatile("cp.async.wait_group 1;\n");
        else              asm volatile("cp.async.wait_group 0;\n");
        __syncthreads();
        if (it + 2 < NCH) load_chunk(it + 2);  // overwrites buf consumed at it-1

        const uint32_t sa = sBase + (it % NSTG) * STG_BYTES;
        const uint32_t sb = sa + AREG_B;

        uint32_t af[2][4][4];
        uint32_t bf[2][4][2];

        auto ldfrag = [&](int buf, int ks) {
#pragma unroll
            for (int mi = 0; mi < 4; ++mi) {
                int r = a_row + mi * 16;
                int ci = ks * 2 + a_c4;
                uint32_t addr = sa + r * 128 + ((ci ^ (r & 7)) << 4);
                asm volatile(
                    "ldmatrix.sync.aligned.m8n8.x4.shared.b16 {%0,%1,%2,%3},[%4];\n"
                    : "=r"(af[buf][mi][0]), "=r"(af[buf][mi][1]),
                      "=r"(af[buf][mi][2]), "=r"(af[buf][mi][3])
                    : "r"(addr));
            }
#pragma unroll
            for (int np = 0; np < 2; ++np) {
                int r = b_row + np * 16;
                int ci = ks * 2 + b_c4;
                uint32_t addr = sb + r * 128 + ((ci ^ (r & 7)) << 4);
                uint32_t r0, r1, r2, r3;
                asm volatile(
                    "ldmatrix.sync.aligned.m8n8.x4.shared.b16 {%0,%1,%2,%3},[%4];\n"
                    : "=r"(r0), "=r"(r1), "=r"(r2), "=r"(r3) : "r"(addr));
                bf[buf][np * 2][0] = r0;     bf[buf][np * 2][1] = r1;
                bf[buf][np * 2 + 1][0] = r2; bf[buf][np * 2 + 1][1] = r3;
            }
        };

        ldfrag(0, 0);
#pragma unroll
        for (int ks = 0; ks < 4; ++ks) {    // 4 k8-steps per 32-float chunk
            if (ks < 3) ldfrag((ks + 1) & 1, ks + 1);
            const int cur = ks & 1;
#pragma unroll
            for (int mi = 0; mi < 4; ++mi)
#pragma unroll
                for (int ni = 0; ni < 4; ++ni) {
                    asm volatile(
                        "mma.sync.aligned.m16n8k8.row.col.f32.tf32.tf32.f32 "
                        "{%0,%1,%2,%3},{%4,%5,%6,%7},{%8,%9},{%0,%1,%2,%3};\n"
                        : "+f"(acc[mi][ni][0]), "+f"(acc[mi][ni][1]),
                          "+f"(acc[mi][ni][2]), "+f"(acc[mi][ni][3])
                        : "r"(af[cur][mi][0]), "r"(af[cur][mi][1]),
                          "r"(af[cur][mi][2]), "r"(af[cur][mi][3]),
                          "r"(bf[cur][ni][0]), "r"(bf[cur][ni][1]));
                }
        }
    }

    // epilogue: c-frag rows g / g+8, cols 2*(lane&3), 2*(lane&3)+1
    const int g = lane >> 2;
    const int cc = (lane & 3) * 2;
#pragma unroll
    for (int mi = 0; mi < 4; ++mi) {
#pragma unroll
        for (int ni = 0; ni < 4; ++ni) {
            int row = m0 + wm + mi * 16 + g;
            int col = n0 + wn + ni * 8 + cc;
            *(float2*)(C + (size_t)row * Nn + col) =
                make_float2(acc[mi][ni][0], acc[mi][ni][1]);
            *(float2*)(C + (size_t)(row + 8) * Nn + col) =
                make_float2(acc[mi][ni][2], acc[mi][ni][3]);
        }
    }

    // fused column sums over this warp's 64 rows (deterministic, no atomics)
    if (do_colsum) {
        float cs[4][2];
#pragma unroll
        for (int ni = 0; ni < 4; ++ni) {
            float s0 = 0.0f, s1 = 0.0f;
#pragma unroll
            for (int mi = 0; mi < 4; ++mi) {
                s0 += acc[mi][ni][0] + acc[mi][ni][2];
                s1 += acc[mi][ni][1] + acc[mi][ni][3];
            }
            cs[ni][0] = s0;
            cs[ni][1] = s1;
        }
#pragma unroll
        for (int off = 4; off < 32; off <<= 1) {
#pragma unroll
            for (int ni = 0; ni < 4; ++ni) {
                cs[ni][0] += __shfl_xor_sync(0xffffffffu, cs[ni][0], off);
                cs[ni][1] += __shfl_xor_sync(0xffffffffu, cs[ni][1], off);
            }
        }
        if (lane < 4) {
            int slot = (m0 >> 7) * 2 + (wm >> 6);   // 0..31
#pragma unroll
            for (int ni = 0; ni < 4; ++ni) {
                g_cp[slot][n0 + wn + ni * 8 + lane * 2]     = cs[ni][0];
                g_cp[slot][n0 + wn + ni * 8 + lane * 2 + 1] = cs[ni][1];
            }
        }
    }
}

// ---------------------------------------------------------------------------
// Fusion MLP with INLINE cvec (mean from g_cp partials).
// Per (64-token tile, head) block: two 64x64x64 GEMMs with exact GELU.
// Writes multi as tf32-rounded fp32 (single float4 store).
// ---------------------------------------------------------------------------
__device__ __forceinline__ float gelu_exact(float x) {
    return 0.5f * x * (1.0f + erff(x * 0.70710678118654752f));
}

__global__ __launch_bounds__(256) void fusion_kernel(
    const float* __restrict__ fuW1, const float* __restrict__ fub1,
    const float* __restrict__ fuW2, const float* __restrict__ fub2)
{
    __shared__ float aT[HD][68];
    __shared__ float bT[HD][68];
    __shared__ float mnS[HD];
    __shared__ float cvS[HD];

    const int tid = threadIdx.x;
    const int m0 = blockIdx.x * 64;
    const int h = blockIdx.y;
    const int b = m0 >> 10;
    const int tr = tid >> 4;
    const int tc = tid & 15;

    // sequence mean for this (b, h) slice from the 16 GEMM-epilogue partials
    if (tid < HD) {
        int c = h * HD + tid;
        float s = 0.0f;
#pragma unroll
        for (int q = 0; q < 16; ++q)
            s += g_cp[b * 16 + q][c];
        mnS[tid] = s * (1.0f / 1024.0f);
    }

    for (int idx = tid; idx < 64 * 64; idx += 256) {
        int t = idx >> 6, e = idx & 63;
        aT[e][t] = g_HF[(size_t)(m0 + t) * DMODEL + h * HD + e];
    }
    for (int idx = tid; idx < 64 * 64; idx += 256) {
        int j = idx >> 6, e = idx & 63;
        bT[e][j] = fuW1[(size_t)(h * HD + j) * (3 * HD) + e];
    }
    __syncthreads();

    // inline cvec: 4 threads per j-row, each covers 16 e's (float4 reads)
    {
        const int j = tid >> 2;          // 0..63
        const int t = tid & 3;           // 0..3
        const float* wrow = fuW1 + (size_t)(h * HD + j) * (3 * HD);
        float cacc = 0.0f;
#pragma unroll
        for (int q = 0; q < 4; ++q) {
            int e = t * 16 + q * 4;
            float4 wa = *(const float4*)(wrow + 64 + e);
            float4 wb = *(const float4*)(wrow + 128 + e);
            cacc = fmaf(wa.x + wb.x, mnS[e + 0], cacc);
            cacc = fmaf(wa.y + wb.y, mnS[e + 1], cacc);
            cacc = fmaf(wa.z + wb.z, mnS[e + 2], cacc);
            cacc = fmaf(wa.w + wb.w, mnS[e + 3], cacc);
        }
        cacc += __shfl_down_sync(0xffffffffu, cacc, 1, 4);
        cacc += __shfl_down_sync(0xffffffffu, cacc, 2, 4);
        if (t == 0) cvS[j] = cacc + fub1[h * HD + j];
    }

    float acc[4][4];
#pragma unroll
    for (int i = 0; i < 4; ++i)
#pragma unroll
        for (int j = 0; j < 4; ++j) acc[i][j] = 0.0f;

#pragma unroll
    for (int e = 0; e < HD; ++e) {
        float4 a = *(const float4*)&aT[e][tr * 4];
        float4 bv = *(const float4*)&bT[e][tc * 4];
        float ra[4] = {a.x, a.y, a.z, a.w};
        float rb[4] = {bv.x, bv.y, bv.z, bv.w};
#pragma unroll
        for (int i = 0; i < 4; ++i)
#pragma unroll
            for (int j = 0; j < 4; ++j)
                acc[i][j] = fmaf(ra[i], rb[j], acc[i][j]);
    }
    __syncthreads();   // aT/bT reads done; cvS written (synced here)

#pragma unroll
    for (int jj = 0; jj < 4; ++jj) {
        int j = tc * 4 + jj;
        float cv = cvS[j];
        float4 gv;
        gv.x = gelu_exact(acc[0][jj] + cv);
        gv.y = gelu_exact(acc[1][jj] + cv);
        gv.z = gelu_exact(acc[2][jj] + cv);
        gv.w = gelu_exact(acc[3][jj] + cv);
        *(float4*)&aT[j][tr * 4] = gv;
    }
    for (int idx = tid; idx < 64 * 64; idx += 256) {
        int f = idx >> 6, j = idx & 63;
        bT[j][f] = fuW2[(size_t)(h * HD + f) * HD + j];
    }
    __syncthreads();

    float acc2[4][4];
#pragma unroll
    for (int i = 0; i < 4; ++i)
#pragma unroll
        for (int j = 0; j < 4; ++j) acc2[i][j] = 0.0f;

#pragma unroll
    for (int j = 0; j < HD; ++j) {
        float4 a = *(const float4*)&aT[j][tr * 4];
        float4 bv = *(const float4*)&bT[j][tc * 4];
        float ra[4] = {a.x, a.y, a.z, a.w};
        float rb[4] = {bv.x, bv.y, bv.z, bv.w};
#pragma unroll
        for (int i = 0; i < 4; ++i)
#pragma unroll
            for (int jj = 0; jj < 4; ++jj)
                acc2[i][jj] = fmaf(ra[i], rb[jj], acc2[i][jj]);
    }

    float bias[4];
#pragma unroll
    for (int jj = 0; jj < 4; ++jj) bias[jj] = fub2[h * HD + tc * 4 + jj];

#pragma unroll
    for (int i = 0; i < 4; ++i) {
        int t = tr * 4 + i;
        float4 o;
        o.x = tf32r(acc2[i][0] + bias[0]);
        o.y = tf32r(acc2[i][1] + bias[1]);
        o.z = tf32r(acc2[i][2] + bias[2]);
        o.w = tf32r(acc2[i][3] + bias[3]);
        *(float4*)&g_multiT[(size_t)(m0 + t) * DMODEL + h * HD + tc * 4] = o;
    }
}

// ---------------------------------------------------------------------------
// Trivial outputs: fwd/bwd targets + avg_strength (analytic constants)
// ---------------------------------------------------------------------------
__global__ void extras_kernel(const int* __restrict__ prev,
                              const float* __restrict__ cr,
                              float* __restrict__ out)
{
    int idx = blockIdx.x * blockDim.x + threadIdx.x;
    if (idx >= NTOK) return;
    int n = idx & (NSEQ - 1);

    float thr = floorf((float)NSEQ / (1.0f + expf(-cr[0])));
    float fwd = 511.0f;
    if ((float)n >= thr) {
        int p = prev[idx];
        p = p < 0 ? 0 : (p > NSEQ - 1 ? NSEQ - 1 : p);
        fwd = (float)p;
    }
    out[OFF_FWD + idx] = fwd;
    out[OFF_BWD + idx] = 511.0f;
    out[OFF_STR + idx] = 1.0f - logf(1.0f / (float)NSEQ + 1e-8f);
}

// ---------------------------------------------------------------------------
extern "C" void kernel_launch(void* const* d_in, const int* in_sizes, int n_in,
                              void* d_out, int out_size)
{
    const float* h    = (const float*)d_in[0];
    const int*   prev = (const int*)d_in[1];
    // d_in[2..9]: forward/backward encoder weights — provably dead code
    const float* Wv   = (const float*)d_in[10];
    const float* fuW1 = (const float*)d_in[11];
    const float* fub1 = (const float*)d_in[12];
    const float* fuW2 = (const float*)d_in[13];
    const float* fub2 = (const float*)d_in[14];
    const float* Wo   = (const float*)d_in[15];
    const float* cr   = (const float*)d_in[16];
    float* out = (float*)d_out;

    float *pHF = nullptr, *phT = nullptr, *pWvT = nullptr, *pWoT = nullptr,
          *pMT = nullptr;
    cudaGetSymbolAddress((void**)&pHF, g_HF);
    cudaGetSymbolAddress((void**)&phT, g_hT);
    cudaGetSymbolAddress((void**)&pWvT, g_WvT);
    cudaGetSymbolAddress((void**)&pWoT, g_WoT);
    cudaGetSymbolAddress((void**)&pMT, g_multiT);

    cudaFuncSetAttribute(gemm_tf32_nt,
                         cudaFuncAttributeMaxDynamicSharedMemorySize, GEMM_SMEM);

    // 0) tf32-RN converts in one launch
    tf32_all<<<4096, 256>>>(h, Wv, Wo);

    dim3 g1(DMODEL / TILE_N, NTOK / TILE_M);   // (16, 16) = 256 CTAs

    // 1) head_features = h @ Wv^T  (tf32 mma) + fused column sums
    gemm_tf32_nt<<<g1, 128, GEMM_SMEM>>>(phT, pWvT, pHF, DMODEL, 1);

    // 2) fusion MLP (inline cvec; mean from g_cp) -> g_multiT (tf32 fp32)
    fusion_kernel<<<dim3(NTOK / 64, NH), 256>>>(fuW1, fub1, fuW2, fub2);

    // 3) final_output = multi @ Wo^T
    gemm_tf32_nt<<<g1, 128, GEMM_SMEM>>>(pMT, pWoT, out, DMODEL, 0);

    // 4) analytic outputs
    extras_kernel<<<(NTOK + 255) / 256, 256>>>(prev, cr, out);
}